// round 16
// baseline (speedup 1.0000x reference)
#include <cuda_runtime.h>
#include <cuda_bf16.h>
#include <cuda_fp16.h>
#include <cstdint>

#define N_NODES 100000
#define N_EDGES 1600000
#define FEAT 128
#define N_GRAPHS 100
#define POOL_SEGS 8

#define SCAN_ITEMS 1024
#define SCAN_BLOCKS ((N_NODES + SCAN_ITEMS - 1) / SCAN_ITEMS)  // 98

// Scratch (allocation-free rule: __device__ globals)
__device__ float   g_bufA[(size_t)N_NODES * FEAT];
__device__ float   g_bufB[(size_t)N_NODES * FEAT];
__device__ __half2 g_h16[(size_t)N_NODES * 64];   // fp16 mirror for gathers (256B/row)
__device__ float   g_poolacc[N_GRAPHS * FEAT];
__device__ int   g_deg[N_NODES];
__device__ int   g_rowptr[N_NODES + 1];
__device__ int   g_cursor[N_NODES];
__device__ int   g_csrsrc[N_EDGES];
__device__ int   g_blocksum[SCAN_BLOCKS];
__device__ int   g_blockoff[SCAN_BLOCKS];
__device__ int   g_idx64;

// ===========================================================================
// Helpers
// ===========================================================================
__device__ __forceinline__ uint32_t smem_u32(const void* p) {
    uint32_t a;
    asm("{ .reg .u64 t; cvta.to.shared.u64 t, %1; cvt.u32.u64 %0, t; }" : "=r"(a) : "l"(p));
    return a;
}
__device__ __forceinline__ uint32_t pack_bf16(float a, float b) {  // {lo=a, hi=b}
    uint32_t r;
    asm("cvt.rn.bf16x2.f32 %0, %1, %2;" : "=r"(r) : "f"(b), "f"(a));
    return r;
}
__device__ __forceinline__ void ldsm_x4(uint32_t* r, uint32_t addr) {
    asm volatile("ldmatrix.sync.aligned.m8n8.x4.shared.b16 {%0,%1,%2,%3}, [%4];"
        : "=r"(r[0]), "=r"(r[1]), "=r"(r[2]), "=r"(r[3]) : "r"(addr));
}
__device__ __forceinline__ void mma_bf16(float* c, const uint32_t* a, const uint32_t* b) {
    asm volatile("mma.sync.aligned.m16n8k16.row.col.f32.bf16.bf16.f32 "
        "{%0,%1,%2,%3}, {%4,%5,%6,%7}, {%8,%9}, {%0,%1,%2,%3};"
        : "+f"(c[0]), "+f"(c[1]), "+f"(c[2]), "+f"(c[3])
        : "r"(a[0]), "r"(a[1]), "r"(a[2]), "r"(a[3]), "r"(b[0]), "r"(b[1]));
}
__device__ __forceinline__ void cp16(uint32_t saddr, const void* gptr) {
    asm volatile("cp.async.cg.shared.global [%0], [%1], 16;" :: "r"(saddr), "l"(gptr));
}
#define CP_COMMIT() asm volatile("cp.async.commit_group;" ::: "memory")
#define CP_WAIT0()  asm volatile("cp.async.wait_group 0;" ::: "memory")

// ===========================================================================
// Index dtype detector (int64 little-endian => odd words zero). 1 warp.
// ===========================================================================
__global__ void detect_kernel(const int* __restrict__ ei_words) {
    const int lane = threadIdx.x;
    int ok = 1;
#pragma unroll
    for (int j = 0; j < 16; j++) {
        int i = j * 32 + lane;
        int lo = ei_words[2 * i];
        int hi = ei_words[2 * i + 1];
        if (hi != 0 || lo < 0 || lo >= N_NODES) ok = 0;
    }
    int all = __all_sync(0xffffffffu, ok);
    if (lane == 0) g_idx64 = all;
}
__device__ __forceinline__ int load_idx(const void* p, long long i) {
    return g_idx64 ? (int)((const long long*)p)[i] : ((const int*)p)[i];
}

// ===========================================================================
// CSR build
// ===========================================================================
__global__ void hist_kernel(const void* __restrict__ ei, int* __restrict__ deg) {
    int e = blockIdx.x * blockDim.x + threadIdx.x;
    if (e >= N_EDGES) return;
    atomicAdd(&deg[load_idx(ei, (long long)N_EDGES + e)], 1);
}
__global__ void scanA_kernel(const int* __restrict__ deg, int* __restrict__ blocksum) {
    __shared__ int red[256];
    const int t = threadIdx.x;
    const int base = blockIdx.x * SCAN_ITEMS;
    int s = 0;
#pragma unroll
    for (int j = 0; j < 4; j++) {
        int i = base + t + j * 256;
        if (i < N_NODES) s += deg[i];
    }
    red[t] = s;
    __syncthreads();
    for (int off = 128; off > 0; off >>= 1) {
        if (t < off) red[t] += red[t + off];
        __syncthreads();
    }
    if (t == 0) blocksum[blockIdx.x] = red[0];
}
__global__ void scanB_kernel(const int* __restrict__ blocksum,
                             int* __restrict__ blockoff, int* __restrict__ rowptr) {
    __shared__ int v[128];
    const int t = threadIdx.x;
    v[t] = (t < SCAN_BLOCKS) ? blocksum[t] : 0;
    __syncthreads();
    int mine = v[t];
    for (int off = 1; off < 128; off <<= 1) {
        int tmp = (t >= off) ? v[t - off] : 0;
        __syncthreads();
        v[t] += tmp;
        __syncthreads();
    }
    if (t < SCAN_BLOCKS) blockoff[t] = v[t] - mine;
    if (t == 127) rowptr[N_NODES] = v[127];
}
__global__ void scanC_kernel(const int* __restrict__ deg, const int* __restrict__ blockoff,
                             int* __restrict__ rowptr, int* __restrict__ cursor) {
    __shared__ int ts[256];
    const int t = threadIdx.x;
    const int base = blockIdx.x * SCAN_ITEMS + t * 4;
    int d0 = 0, d1 = 0, d2 = 0, d3 = 0;
    if (base + 0 < N_NODES) d0 = deg[base + 0];
    if (base + 1 < N_NODES) d1 = deg[base + 1];
    if (base + 2 < N_NODES) d2 = deg[base + 2];
    if (base + 3 < N_NODES) d3 = deg[base + 3];
    int tot = d0 + d1 + d2 + d3;
    ts[t] = tot;
    __syncthreads();
    for (int off = 1; off < 256; off <<= 1) {
        int tmp = (t >= off) ? ts[t - off] : 0;
        __syncthreads();
        ts[t] += tmp;
        __syncthreads();
    }
    int run = blockoff[blockIdx.x] + ts[t] - tot;
    if (base + 0 < N_NODES) { rowptr[base + 0] = run; cursor[base + 0] = run; run += d0; }
    if (base + 1 < N_NODES) { rowptr[base + 1] = run; cursor[base + 1] = run; run += d1; }
    if (base + 2 < N_NODES) { rowptr[base + 2] = run; cursor[base + 2] = run; run += d2; }
    if (base + 3 < N_NODES) { rowptr[base + 3] = run; cursor[base + 3] = run; run += d3; }
}
__global__ void fill_kernel(const void* __restrict__ ei,
                            int* __restrict__ cursor, int* __restrict__ csrsrc) {
    int e = blockIdx.x * blockDim.x + threadIdx.x;
    if (e >= N_EDGES) return;
    int s = load_idx(ei, e);
    int d = load_idx(ei, (long long)N_EDGES + e);
    csrsrc[atomicAdd(&cursor[d], 1)] = s;
}

// ===========================================================================
// fp32 -> fp16 mirror convert
// ===========================================================================
__global__ void tohalf_kernel(const float* __restrict__ src, __half2* __restrict__ dst) {
    const int i = blockIdx.x * blockDim.x + threadIdx.x;   // float4 index
    if (i >= N_NODES * 32) return;
    float4 v = ((const float4*)src)[i];
    dst[2 * i + 0] = __floats2half2_rn(v.x, v.y);
    dst[2 * i + 1] = __floats2half2_rn(v.z, v.w);
}

// ===========================================================================
// GIN aggregation: out[n] = self[n](fp32) + sum_nbr h16[src](fp16, 256B rows).
// One warp per node; csrsrc chunk loads software-pipelined (R15 structure).
// ===========================================================================
__global__ void __launch_bounds__(256)
agg_kernel(const float* __restrict__ self, const __half2* __restrict__ nbr,
           float* __restrict__ out,
           const int* __restrict__ rowptr, const int* __restrict__ csrsrc) {
    const int n = blockIdx.x * 8 + (threadIdx.x >> 5);
    if (n >= N_NODES) return;
    const int lane = threadIdx.x & 31;
    const int beg = rowptr[n];
    const int end = rowptr[n + 1];
    float4 acc = ((const float4*)(self + (size_t)n * FEAT))[lane];

    int base = beg;
    int sid = (base + lane < end) ? csrsrc[base + lane] : 0;  // prefetched chunk
    while (base < end) {
        const int cnt = min(32, end - base);
        const int nb = base + 32;
        int sid_next = (nb + lane < end) ? csrsrc[nb + lane] : 0;  // prefetch next
#pragma unroll 4
        for (int j = 0; j < cnt; j++) {
            int s = __shfl_sync(0xffffffffu, sid, j);
            uint2 w = ((const uint2*)(nbr + (size_t)s * 64))[lane];
            __half2 p0 = *reinterpret_cast<__half2*>(&w.x);
            __half2 p1 = *reinterpret_cast<__half2*>(&w.y);
            float2 f0 = __half22float2(p0);
            float2 f1 = __half22float2(p1);
            acc.x += f0.x; acc.y += f0.y; acc.z += f1.x; acc.w += f1.y;
        }
        sid = sid_next;
        base = nb;
    }
    ((float4*)(out + (size_t)n * FEAT))[lane] = acc;
}

// ===========================================================================
// Fused persistent MLP (two bf16-split HMMA GEMMs), R8/R15 structure:
//   C = relu( relu(A@W1^T + b1) @ W2^T + b2 );  optional fp16 mirror of C.
// ===========================================================================
#define SAB 136
#define WTILE_B (128 * SAB * 2)
#define ATILE_B (64 * SAB * 2)
#define STG_F   132
#define SMF_B1   0
#define SMF_B2   512
#define SMF_W1H  1024
#define SMF_W1L  (SMF_W1H + WTILE_B)
#define SMF_W2H  (SMF_W1H + 2 * WTILE_B)
#define SMF_W2L  (SMF_W1H + 3 * WTILE_B)
#define SMF_AH   (SMF_W1H + 4 * WTILE_B)
#define SMF_AL   (SMF_AH + ATILE_B)
#define SMF_STG  (SMF_AL + ATILE_B)
#define SMF_TOTAL (SMF_STG + 64 * STG_F * 4)  // 208896
#define GEMM_GRID 148

__global__ void __launch_bounds__(256)
mlp_fused_kernel(const float* __restrict__ A,
                 const float* __restrict__ W1, const float* __restrict__ b1,
                 const float* __restrict__ W2, const float* __restrict__ b2,
                 float* __restrict__ C, __half2* __restrict__ h16out, int M) {
    extern __shared__ char smem[];
    const uint32_t sb = smem_u32(smem);
    const int tid = threadIdx.x;
    const int lane = tid & 31;
    const int wid = tid >> 5;
    const int numTiles = (M + 63) >> 6;

    float* stg = (float*)(smem + SMF_STG);

    int tile = blockIdx.x;
    if (tile < numTiles) {
        const int row0 = tile << 6;
#pragma unroll
        for (int j = 0; j < 8; j++) {
            const int i = tid + j * 256;
            const int r = i >> 5, c16 = i & 31;
            if (row0 + r < M)
                cp16(sb + SMF_STG + (uint32_t)(r * STG_F + c16 * 4) * 4,
                     A + (size_t)(row0 + r) * FEAT + c16 * 4);
        }
    }
    CP_COMMIT();

    if (tid < 128) ((float*)(smem + SMF_B1))[tid] = b1[tid];
    else           ((float*)(smem + SMF_B2))[tid - 128] = b2[tid - 128];
    {
        const int r = tid >> 1;
        const int half = tid & 1;
        const float4* w1row = (const float4*)(W1 + (size_t)r * FEAT);
        const float4* w2row = (const float4*)(W2 + (size_t)r * FEAT);
#pragma unroll
        for (int j = 0; j < 16; j++) {
            const int col = half * 64 + j * 4;
            const uint32_t off = (uint32_t)(r * SAB + col) * 2;
            float4 v1 = w1row[half * 16 + j];
            float a0 = __bfloat162float(__float2bfloat16_rn(v1.x));
            float a1 = __bfloat162float(__float2bfloat16_rn(v1.y));
            float a2 = __bfloat162float(__float2bfloat16_rn(v1.z));
            float a3 = __bfloat162float(__float2bfloat16_rn(v1.w));
            *(uint2*)(smem + SMF_W1H + off) = make_uint2(pack_bf16(a0, a1), pack_bf16(a2, a3));
            *(uint2*)(smem + SMF_W1L + off) =
                make_uint2(pack_bf16(v1.x - a0, v1.y - a1), pack_bf16(v1.z - a2, v1.w - a3));
            float4 v2 = w2row[half * 16 + j];
            float c0 = __bfloat162float(__float2bfloat16_rn(v2.x));
            float c1 = __bfloat162float(__float2bfloat16_rn(v2.y));
            float c2 = __bfloat162float(__float2bfloat16_rn(v2.z));
            float c3 = __bfloat162float(__float2bfloat16_rn(v2.w));
            *(uint2*)(smem + SMF_W2H + off) = make_uint2(pack_bf16(c0, c1), pack_bf16(c2, c3));
            *(uint2*)(smem + SMF_W2L + off) =
                make_uint2(pack_bf16(v2.x - c0, v2.y - c1), pack_bf16(v2.z - c2, v2.w - c3));
        }
    }

    const int m0 = (wid & 1) * 32;
    const int n0 = (wid >> 1) * 32;
    const int g = lane >> 3, rr = lane & 7;
    uint32_t aH0[2], aL0[2], b1H[2], b1L[2], b2H[2], b2L[2];
#pragma unroll
    for (int mb = 0; mb < 2; mb++) {
        const uint32_t o = (uint32_t)((m0 + mb * 16 + (g & 1) * 8 + rr) * SAB + (g >> 1) * 8) * 2;
        aH0[mb] = sb + SMF_AH + o;
        aL0[mb] = sb + SMF_AL + o;
    }
#pragma unroll
    for (int p = 0; p < 2; p++) {
        const uint32_t o = (uint32_t)((n0 + p * 16 + (g >> 1) * 8 + rr) * SAB + (g & 1) * 8) * 2;
        b1H[p] = sb + SMF_W1H + o;
        b1L[p] = sb + SMF_W1L + o;
        b2H[p] = sb + SMF_W2H + o;
        b2L[p] = sb + SMF_W2L + o;
    }
    const float* bs1 = (const float*)(smem + SMF_B1);
    const float* bs2 = (const float*)(smem + SMF_B2);

    for (; tile < numTiles; tile += GEMM_GRID) {
        const int row0 = tile << 6;

        CP_WAIT0();
        __syncthreads();

        {
            const int r = tid >> 2;
            const int q = tid & 3;
            const bool in = (row0 + r < M);
            const float* srow = stg + r * STG_F + q * 32;
#pragma unroll
            for (int j = 0; j < 8; j++) {
                const int col = q * 32 + j * 4;
                const uint32_t off = (uint32_t)(r * SAB + col) * 2;
                float4 va = in ? *(const float4*)(srow + j * 4) : make_float4(0.f, 0.f, 0.f, 0.f);
                float h0 = __bfloat162float(__float2bfloat16_rn(va.x));
                float h1 = __bfloat162float(__float2bfloat16_rn(va.y));
                float h2 = __bfloat162float(__float2bfloat16_rn(va.z));
                float h3 = __bfloat162float(__float2bfloat16_rn(va.w));
                *(uint2*)(smem + SMF_AH + off) = make_uint2(pack_bf16(h0, h1), pack_bf16(h2, h3));
                *(uint2*)(smem + SMF_AL + off) =
                    make_uint2(pack_bf16(va.x - h0, va.y - h1), pack_bf16(va.z - h2, va.w - h3));
            }
        }
        __syncthreads();

        const int nt = tile + GEMM_GRID;
        if (nt < numTiles) {
            const int nrow0 = nt << 6;
#pragma unroll
            for (int j = 0; j < 8; j++) {
                const int i = tid + j * 256;
                const int r = i >> 5, c16 = i & 31;
                if (nrow0 + r < M)
                    cp16(sb + SMF_STG + (uint32_t)(r * STG_F + c16 * 4) * 4,
                         A + (size_t)(nrow0 + r) * FEAT + c16 * 4);
            }
        }
        CP_COMMIT();

        // ================= GEMM1 =================
        float acc[2][4][4];
#pragma unroll
        for (int mb = 0; mb < 2; mb++)
#pragma unroll
            for (int o = 0; o < 4; o++)
#pragma unroll
                for (int q = 0; q < 4; q++) acc[mb][o][q] = 0.f;
        {
            uint32_t aH_[2] = {aH0[0], aH0[1]}, aL_[2] = {aL0[0], aL0[1]};
            uint32_t bH_[2] = {b1H[0], b1H[1]}, bL_[2] = {b1L[0], b1L[1]};
#pragma unroll
            for (int kk = 0; kk < 8; kk++) {
                uint32_t ah[2][4], al[2][4], bb[2][4];
                ldsm_x4(ah[0], aH_[0]); ldsm_x4(ah[1], aH_[1]);
                ldsm_x4(al[0], aL_[0]); ldsm_x4(al[1], aL_[1]);
                ldsm_x4(bb[0], bH_[0]); ldsm_x4(bb[1], bH_[1]);
#pragma unroll
                for (int mb = 0; mb < 2; mb++)
#pragma unroll
                    for (int o = 0; o < 4; o++) {
                        const uint32_t* b = &bb[o >> 1][(o & 1) * 2];
                        mma_bf16(acc[mb][o], ah[mb], b);
                        mma_bf16(acc[mb][o], al[mb], b);
                    }
                ldsm_x4(bb[0], bL_[0]); ldsm_x4(bb[1], bL_[1]);
#pragma unroll
                for (int mb = 0; mb < 2; mb++)
#pragma unroll
                    for (int o = 0; o < 4; o++)
                        mma_bf16(acc[mb][o], ah[mb], &bb[o >> 1][(o & 1) * 2]);
#pragma unroll
                for (int i = 0; i < 2; i++) { aH_[i] += 32; aL_[i] += 32; bH_[i] += 32; bL_[i] += 32; }
            }
        }
        __syncthreads();

        // ---- h1 = relu(acc + b1) split-packed into A buffers ----
#pragma unroll
        for (int mb = 0; mb < 2; mb++) {
            const int r0 = m0 + mb * 16 + (lane >> 2);
#pragma unroll
            for (int o = 0; o < 4; o++) {
                const int col = n0 + o * 8 + (lane & 3) * 2;
                const float c0 = bs1[col], c1 = bs1[col + 1];
                const uint32_t off0 = (uint32_t)(r0 * SAB + col) * 2;
                const uint32_t off8 = (uint32_t)((r0 + 8) * SAB + col) * 2;
                float v0 = fmaxf(acc[mb][o][0] + c0, 0.f);
                float v1 = fmaxf(acc[mb][o][1] + c1, 0.f);
                float h0 = __bfloat162float(__float2bfloat16_rn(v0));
                float h1 = __bfloat162float(__float2bfloat16_rn(v1));
                *(uint32_t*)(smem + SMF_AH + off0) = pack_bf16(h0, h1);
                *(uint32_t*)(smem + SMF_AL + off0) = pack_bf16(v0 - h0, v1 - h1);
                float v2 = fmaxf(acc[mb][o][2] + c0, 0.f);
                float v3 = fmaxf(acc[mb][o][3] + c1, 0.f);
                float h2 = __bfloat162float(__float2bfloat16_rn(v2));
                float h3 = __bfloat162float(__float2bfloat16_rn(v3));
                *(uint32_t*)(smem + SMF_AH + off8) = pack_bf16(h2, h3);
                *(uint32_t*)(smem + SMF_AL + off8) = pack_bf16(v2 - h2, v3 - h3);
            }
        }
        __syncthreads();

        // ================= GEMM2 =================
#pragma unroll
        for (int mb = 0; mb < 2; mb++)
#pragma unroll
            for (int o = 0; o < 4; o++)
#pragma unroll
                for (int q = 0; q < 4; q++) acc[mb][o][q] = 0.f;
        {
            uint32_t aH_[2] = {aH0[0], aH0[1]}, aL_[2] = {aL0[0], aL0[1]};
            uint32_t bH_[2] = {b2H[0], b2H[1]}, bL_[2] = {b2L[0], b2L[1]};
#pragma unroll
            for (int kk = 0; kk < 8; kk++) {
                uint32_t ah[2][4], al[2][4], bb[2][4];
                ldsm_x4(ah[0], aH_[0]); ldsm_x4(ah[1], aH_[1]);
                ldsm_x4(al[0], aL_[0]); ldsm_x4(al[1], aL_[1]);
                ldsm_x4(bb[0], bH_[0]); ldsm_x4(bb[1], bH_[1]);
#pragma unroll
                for (int mb = 0; mb < 2; mb++)
#pragma unroll
                    for (int o = 0; o < 4; o++) {
                        const uint32_t* b = &bb[o >> 1][(o & 1) * 2];
                        mma_bf16(acc[mb][o], ah[mb], b);
                        mma_bf16(acc[mb][o], al[mb], b);
                    }
                ldsm_x4(bb[0], bL_[0]); ldsm_x4(bb[1], bL_[1]);
#pragma unroll
                for (int mb = 0; mb < 2; mb++)
#pragma unroll
                    for (int o = 0; o < 4; o++)
                        mma_bf16(acc[mb][o], ah[mb], &bb[o >> 1][(o & 1) * 2]);
#pragma unroll
                for (int i = 0; i < 2; i++) { aH_[i] += 32; aL_[i] += 32; bH_[i] += 32; bL_[i] += 32; }
            }
        }
        __syncthreads();

        // ---- epilogue: relu(acc + b2) -> C (+ optional fp16 mirror) ----
#pragma unroll
        for (int mb = 0; mb < 2; mb++) {
            const int rbase = row0 + m0 + mb * 16 + (lane >> 2);
#pragma unroll
            for (int o = 0; o < 4; o++) {
                const int col = n0 + o * 8 + (lane & 3) * 2;
                const float c0 = bs2[col], c1 = bs2[col + 1];
                if (rbase < M) {
                    float v0 = fmaxf(acc[mb][o][0] + c0, 0.f);
                    float v1 = fmaxf(acc[mb][o][1] + c1, 0.f);
                    *(float2*)(C + (size_t)rbase * FEAT + col) = make_float2(v0, v1);
                    if (h16out)
                        h16out[(size_t)rbase * 64 + (col >> 1)] = __floats2half2_rn(v0, v1);
                }
                if (rbase + 8 < M) {
                    float v2 = fmaxf(acc[mb][o][2] + c0, 0.f);
                    float v3 = fmaxf(acc[mb][o][3] + c1, 0.f);
                    *(float2*)(C + (size_t)(rbase + 8) * FEAT + col) = make_float2(v2, v3);
                    if (h16out)
                        h16out[(size_t)(rbase + 8) * 64 + (col >> 1)] = __floats2half2_rn(v2, v3);
                }
            }
        }
    }
}

// ===========================================================================
// Two-phase global mean pool (R15)
// ===========================================================================
__device__ __forceinline__ void graph_range(const void* batch, int is64, int gph,
                                            int& start, int& end) {
    const long long* b64 = (const long long*)batch;
    const int* b32 = (const int*)batch;
    int lo = 0, hi = N_NODES;
    while (lo < hi) {
        int mid = (lo + hi) >> 1;
        long long v = is64 ? b64[mid] : (long long)b32[mid];
        if (v < (long long)gph) lo = mid + 1; else hi = mid;
    }
    start = lo;
    hi = N_NODES;
    while (lo < hi) {
        int mid = (lo + hi) >> 1;
        long long v = is64 ? b64[mid] : (long long)b32[mid];
        if (v < (long long)gph + 1) lo = mid + 1; else hi = mid;
    }
    end = lo;
}

__global__ void pool_partial_kernel(const float* __restrict__ h,
                                    const void* __restrict__ batch,
                                    float* __restrict__ poolacc) {
    const int gph = blockIdx.x;
    const int seg = blockIdx.y;
    const int c = threadIdx.x;
    int start, end;
    graph_range(batch, g_idx64, gph, start, end);
    const int len = end - start;
    const int s0 = start + (int)(((long long)len * seg) / POOL_SEGS);
    const int s1 = start + (int)(((long long)len * (seg + 1)) / POOL_SEGS);
    float s = 0.f;
    for (int r = s0; r < s1; r++) s += h[(size_t)r * FEAT + c];
    if (s1 > s0) atomicAdd(&poolacc[gph * FEAT + c], s);
}

__global__ void pool_final_kernel(const float* __restrict__ poolacc,
                                  const void* __restrict__ batch,
                                  float* __restrict__ out_pool) {
    const int gph = blockIdx.x;
    const int c = threadIdx.x;
    int start, end;
    graph_range(batch, g_idx64, gph, start, end);
    out_pool[gph * FEAT + c] = poolacc[gph * FEAT + c] / fmaxf((float)(end - start), 1.f);
}

// ===========================================================================
extern "C" void kernel_launch(void* const* d_in, const int* in_sizes, int n_in,
                              void* d_out, int out_size) {
    const float* x   = (const float*)d_in[0];
    const void*  ei  = d_in[1];
    const void*  bat = d_in[2];
    const float* W1 = (const float*)d_in[3];
    const float* b1 = (const float*)d_in[4];
    const float* W2 = (const float*)d_in[5];
    const float* b2 = (const float*)d_in[6];
    const float* W3 = (const float*)d_in[7];
    const float* b3 = (const float*)d_in[8];
    const float* W4 = (const float*)d_in[9];
    const float* b4 = (const float*)d_in[10];

    float* out      = (float*)d_out;
    float* out_pool = out;
    float* out_h    = out + N_GRAPHS * FEAT;

    float *bufA, *bufB, *poolacc;
    __half2* h16;
    int *deg, *rowptr, *cursor, *csrsrc, *blocksum, *blockoff;
    cudaGetSymbolAddress((void**)&bufA, g_bufA);
    cudaGetSymbolAddress((void**)&bufB, g_bufB);
    cudaGetSymbolAddress((void**)&h16, g_h16);
    cudaGetSymbolAddress((void**)&poolacc, g_poolacc);
    cudaGetSymbolAddress((void**)&deg, g_deg);
    cudaGetSymbolAddress((void**)&rowptr, g_rowptr);
    cudaGetSymbolAddress((void**)&cursor, g_cursor);
    cudaGetSymbolAddress((void**)&csrsrc, g_csrsrc);
    cudaGetSymbolAddress((void**)&blocksum, g_blocksum);
    cudaGetSymbolAddress((void**)&blockoff, g_blockoff);

    cudaFuncSetAttribute(mlp_fused_kernel,
                         cudaFuncAttributeMaxDynamicSharedMemorySize, SMF_TOTAL);

    const int edge_blocks = (N_EDGES + 255) / 256;
    const int cvt_blocks = (N_NODES * 32 + 255) / 256;
    const int agg_blocks = (N_NODES + 7) / 8;

    // ---- CSR build ----
    detect_kernel<<<1, 32>>>((const int*)ei);
    cudaMemsetAsync(deg, 0, N_NODES * sizeof(int));
    cudaMemsetAsync(poolacc, 0, N_GRAPHS * FEAT * sizeof(float));
    hist_kernel<<<edge_blocks, 256>>>(ei, deg);
    scanA_kernel<<<SCAN_BLOCKS, 256>>>(deg, blocksum);
    scanB_kernel<<<1, 128>>>(blocksum, blockoff, rowptr);
    scanC_kernel<<<SCAN_BLOCKS, 256>>>(deg, blockoff, rowptr, cursor);
    fill_kernel<<<edge_blocks, 256>>>(ei, cursor, csrsrc);

    // ---- Layer 1: fp16 mirror of x; gather; MLP emits h1 fp16 mirror ----
    tohalf_kernel<<<cvt_blocks, 256>>>(x, h16);
    agg_kernel<<<agg_blocks, 256>>>(x, h16, bufA, rowptr, csrsrc);
    mlp_fused_kernel<<<GEMM_GRID, 256, SMF_TOTAL>>>(bufA, W1, b1, W2, b2,
                                                    bufB, h16, N_NODES);

    // ---- Layer 2: gather from h1 mirror; MLP -> out_h (no mirror) ----
    agg_kernel<<<agg_blocks, 256>>>(bufB, h16, bufA, rowptr, csrsrc);
    mlp_fused_kernel<<<GEMM_GRID, 256, SMF_TOTAL>>>(bufA, W3, b3, W4, b4,
                                                    out_h, (__half2*)nullptr, N_NODES);

    // ---- Two-phase global mean pool ----
    dim3 pgrid(N_GRAPHS, POOL_SEGS);
    pool_partial_kernel<<<pgrid, FEAT>>>(out_h, bat, poolacc);
    pool_final_kernel<<<N_GRAPHS, FEAT>>>(poolacc, bat, out_pool);
}

// round 17
// speedup vs baseline: 1.0322x; 1.0322x over previous
#include <cuda_runtime.h>
#include <cuda_bf16.h>
#include <cstdint>

#define N_NODES 100000
#define N_EDGES 1600000
#define FEAT 128
#define N_GRAPHS 100
#define POOL_SEGS 8

#define SCAN_ITEMS 1024
#define SCAN_BLOCKS ((N_NODES + SCAN_ITEMS - 1) / SCAN_ITEMS)  // 98

// Scratch (allocation-free rule: __device__ globals)
__device__ float g_bufA[(size_t)N_NODES * FEAT];
__device__ float g_bufB[(size_t)N_NODES * FEAT];
__device__ float g_poolacc[N_GRAPHS * FEAT];
__device__ int   g_deg[N_NODES];
__device__ int   g_rowptr[N_NODES + 1];
__device__ int   g_cursor[N_NODES];
__device__ int   g_csrsrc[N_EDGES];
__device__ int   g_blocksum[SCAN_BLOCKS];
__device__ int   g_blockoff[SCAN_BLOCKS];
__device__ int   g_idx64;

// ===========================================================================
// Helpers
// ===========================================================================
__device__ __forceinline__ uint32_t smem_u32(const void* p) {
    uint32_t a;
    asm("{ .reg .u64 t; cvta.to.shared.u64 t, %1; cvt.u32.u64 %0, t; }" : "=r"(a) : "l"(p));
    return a;
}
__device__ __forceinline__ uint32_t pack_bf16(float a, float b) {  // {lo=a, hi=b}
    uint32_t r;
    asm("cvt.rn.bf16x2.f32 %0, %1, %2;" : "=r"(r) : "f"(b), "f"(a));
    return r;
}
__device__ __forceinline__ void ldsm_x4(uint32_t* r, uint32_t addr) {
    asm volatile("ldmatrix.sync.aligned.m8n8.x4.shared.b16 {%0,%1,%2,%3}, [%4];"
        : "=r"(r[0]), "=r"(r[1]), "=r"(r[2]), "=r"(r[3]) : "r"(addr));
}
__device__ __forceinline__ void mma_bf16(float* c, const uint32_t* a, const uint32_t* b) {
    asm volatile("mma.sync.aligned.m16n8k16.row.col.f32.bf16.bf16.f32 "
        "{%0,%1,%2,%3}, {%4,%5,%6,%7}, {%8,%9}, {%0,%1,%2,%3};"
        : "+f"(c[0]), "+f"(c[1]), "+f"(c[2]), "+f"(c[3])
        : "r"(a[0]), "r"(a[1]), "r"(a[2]), "r"(a[3]), "r"(b[0]), "r"(b[1]));
}
__device__ __forceinline__ void cp16(uint32_t saddr, const void* gptr) {
    asm volatile("cp.async.cg.shared.global [%0], [%1], 16;" :: "r"(saddr), "l"(gptr));
}
#define CP_COMMIT() asm volatile("cp.async.commit_group;" ::: "memory")
#define CP_WAIT0()  asm volatile("cp.async.wait_group 0;" ::: "memory")

// ===========================================================================
// Index dtype detector (int64 little-endian => odd words zero). 1 warp.
// ===========================================================================
__global__ void detect_kernel(const int* __restrict__ ei_words) {
    const int lane = threadIdx.x;
    int ok = 1;
#pragma unroll
    for (int j = 0; j < 16; j++) {
        int i = j * 32 + lane;
        int lo = ei_words[2 * i];
        int hi = ei_words[2 * i + 1];
        if (hi != 0 || lo < 0 || lo >= N_NODES) ok = 0;
    }
    int all = __all_sync(0xffffffffu, ok);
    if (lane == 0) g_idx64 = all;
}
__device__ __forceinline__ int load_idx(const void* p, long long i) {
    return g_idx64 ? (int)((const long long*)p)[i] : ((const int*)p)[i];
}

// ===========================================================================
// CSR build
// ===========================================================================
__global__ void hist_kernel(const void* __restrict__ ei, int* __restrict__ deg) {
    int e = blockIdx.x * blockDim.x + threadIdx.x;
    if (e >= N_EDGES) return;
    atomicAdd(&deg[load_idx(ei, (long long)N_EDGES + e)], 1);
}
__global__ void scanA_kernel(const int* __restrict__ deg, int* __restrict__ blocksum) {
    __shared__ int red[256];
    const int t = threadIdx.x;
    const int base = blockIdx.x * SCAN_ITEMS;
    int s = 0;
#pragma unroll
    for (int j = 0; j < 4; j++) {
        int i = base + t + j * 256;
        if (i < N_NODES) s += deg[i];
    }
    red[t] = s;
    __syncthreads();
    for (int off = 128; off > 0; off >>= 1) {
        if (t < off) red[t] += red[t + off];
        __syncthreads();
    }
    if (t == 0) blocksum[blockIdx.x] = red[0];
}
__global__ void scanB_kernel(const int* __restrict__ blocksum,
                             int* __restrict__ blockoff, int* __restrict__ rowptr) {
    __shared__ int v[128];
    const int t = threadIdx.x;
    v[t] = (t < SCAN_BLOCKS) ? blocksum[t] : 0;
    __syncthreads();
    int mine = v[t];
    for (int off = 1; off < 128; off <<= 1) {
        int tmp = (t >= off) ? v[t - off] : 0;
        __syncthreads();
        v[t] += tmp;
        __syncthreads();
    }
    if (t < SCAN_BLOCKS) blockoff[t] = v[t] - mine;
    if (t == 127) rowptr[N_NODES] = v[127];
}
__global__ void scanC_kernel(const int* __restrict__ deg, const int* __restrict__ blockoff,
                             int* __restrict__ rowptr, int* __restrict__ cursor) {
    __shared__ int ts[256];
    const int t = threadIdx.x;
    const int base = blockIdx.x * SCAN_ITEMS + t * 4;
    int d0 = 0, d1 = 0, d2 = 0, d3 = 0;
    if (base + 0 < N_NODES) d0 = deg[base + 0];
    if (base + 1 < N_NODES) d1 = deg[base + 1];
    if (base + 2 < N_NODES) d2 = deg[base + 2];
    if (base + 3 < N_NODES) d3 = deg[base + 3];
    int tot = d0 + d1 + d2 + d3;
    ts[t] = tot;
    __syncthreads();
    for (int off = 1; off < 256; off <<= 1) {
        int tmp = (t >= off) ? ts[t - off] : 0;
        __syncthreads();
        ts[t] += tmp;
        __syncthreads();
    }
    int run = blockoff[blockIdx.x] + ts[t] - tot;
    if (base + 0 < N_NODES) { rowptr[base + 0] = run; cursor[base + 0] = run; run += d0; }
    if (base + 1 < N_NODES) { rowptr[base + 1] = run; cursor[base + 1] = run; run += d1; }
    if (base + 2 < N_NODES) { rowptr[base + 2] = run; cursor[base + 2] = run; run += d2; }
    if (base + 3 < N_NODES) { rowptr[base + 3] = run; cursor[base + 3] = run; run += d3; }
}
__global__ void fill_kernel(const void* __restrict__ ei,
                            int* __restrict__ cursor, int* __restrict__ csrsrc) {
    int e = blockIdx.x * blockDim.x + threadIdx.x;
    if (e >= N_EDGES) return;
    int s = load_idx(ei, e);
    int d = load_idx(ei, (long long)N_EDGES + e);
    csrsrc[atomicAdd(&cursor[d], 1)] = s;
}

// ===========================================================================
// GIN aggregation (gather, fp32, R15): out[n] = x[n] + sum csrsrc rows.
// One warp per node; csrsrc chunk loads software-pipelined.
// ===========================================================================
__global__ void __launch_bounds__(256)
agg_kernel(const float* __restrict__ x, float* __restrict__ out,
           const int* __restrict__ rowptr, const int* __restrict__ csrsrc) {
    const int n = blockIdx.x * 8 + (threadIdx.x >> 5);
    if (n >= N_NODES) return;
    const int lane = threadIdx.x & 31;
    const int beg = rowptr[n];
    const int end = rowptr[n + 1];
    float4 acc = ((const float4*)(x + (size_t)n * FEAT))[lane];

    int base = beg;
    int sid = (base + lane < end) ? csrsrc[base + lane] : 0;
    while (base < end) {
        const int cnt = min(32, end - base);
        const int nb = base + 32;
        int sid_next = (nb + lane < end) ? csrsrc[nb + lane] : 0;
#pragma unroll 4
        for (int j = 0; j < cnt; j++) {
            int s = __shfl_sync(0xffffffffu, sid, j);
            float4 v = ((const float4*)(x + (size_t)s * FEAT))[lane];
            acc.x += v.x; acc.y += v.y; acc.z += v.z; acc.w += v.w;
        }
        sid = sid_next;
        base = nb;
    }
    ((float4*)(out + (size_t)n * FEAT))[lane] = acc;
}

// ===========================================================================
// Fused persistent MLP (two bf16-split HMMA GEMMs), 512 threads / 16 warps:
//   C = relu( relu(A@W1^T + b1) @ W2^T + b2 )
// Warp tile 32(M) x 16(N): 2 warps along M, 8 along N. 4 warps/SMSP for
// latency hiding (R15 had only 2/SMSP).
// ===========================================================================
#define SAB 136
#define WTILE_B (128 * SAB * 2)
#define ATILE_B (64 * SAB * 2)
#define STG_F   132
#define SMF_B1   0
#define SMF_B2   512
#define SMF_W1H  1024
#define SMF_W1L  (SMF_W1H + WTILE_B)
#define SMF_W2H  (SMF_W1H + 2 * WTILE_B)
#define SMF_W2L  (SMF_W1H + 3 * WTILE_B)
#define SMF_AH   (SMF_W1H + 4 * WTILE_B)
#define SMF_AL   (SMF_AH + ATILE_B)
#define SMF_STG  (SMF_AL + ATILE_B)
#define SMF_TOTAL (SMF_STG + 64 * STG_F * 4)  // 208896
#define GEMM_GRID 148

__global__ void __launch_bounds__(512)
mlp_fused_kernel(const float* __restrict__ A,
                 const float* __restrict__ W1, const float* __restrict__ b1,
                 const float* __restrict__ W2, const float* __restrict__ b2,
                 float* __restrict__ C, int M) {
    extern __shared__ char smem[];
    const uint32_t sb = smem_u32(smem);
    const int tid = threadIdx.x;
    const int lane = tid & 31;
    const int wid = tid >> 5;             // 0..15
    const int numTiles = (M + 63) >> 6;

    float* stg = (float*)(smem + SMF_STG);

    // ---- prefetch first A tile (64 rows x 32 16B-chunks = 2048 chunks) ----
    int tile = blockIdx.x;
    if (tile < numTiles) {
        const int row0 = tile << 6;
#pragma unroll
        for (int j = 0; j < 4; j++) {
            const int i = tid + j * 512;
            const int r = i >> 5, c16 = i & 31;
            if (row0 + r < M)
                cp16(sb + SMF_STG + (uint32_t)(r * STG_F + c16 * 4) * 4,
                     A + (size_t)(row0 + r) * FEAT + c16 * 4);
        }
    }
    CP_COMMIT();

    // ---- biases + one-time W1/W2 split-convert (512 threads: quarter rows) ----
    if (tid < 128) ((float*)(smem + SMF_B1))[tid] = b1[tid];
    else if (tid < 256) ((float*)(smem + SMF_B2))[tid - 128] = b2[tid - 128];
    {
        const int r = tid >> 2;           // 0..127
        const int q = tid & 3;            // 32-col quarter
        const float4* w1row = (const float4*)(W1 + (size_t)r * FEAT);
        const float4* w2row = (const float4*)(W2 + (size_t)r * FEAT);
#pragma unroll
        for (int j = 0; j < 8; j++) {
            const int col = q * 32 + j * 4;
            const uint32_t off = (uint32_t)(r * SAB + col) * 2;
            float4 v1 = w1row[q * 8 + j];
            float a0 = __bfloat162float(__float2bfloat16_rn(v1.x));
            float a1 = __bfloat162float(__float2bfloat16_rn(v1.y));
            float a2 = __bfloat162float(__float2bfloat16_rn(v1.z));
            float a3 = __bfloat162float(__float2bfloat16_rn(v1.w));
            *(uint2*)(smem + SMF_W1H + off) = make_uint2(pack_bf16(a0, a1), pack_bf16(a2, a3));
            *(uint2*)(smem + SMF_W1L + off) =
                make_uint2(pack_bf16(v1.x - a0, v1.y - a1), pack_bf16(v1.z - a2, v1.w - a3));
            float4 v2 = w2row[q * 8 + j];
            float c0 = __bfloat162float(__float2bfloat16_rn(v2.x));
            float c1 = __bfloat162float(__float2bfloat16_rn(v2.y));
            float c2 = __bfloat162float(__float2bfloat16_rn(v2.z));
            float c3 = __bfloat162float(__float2bfloat16_rn(v2.w));
            *(uint2*)(smem + SMF_W2H + off) = make_uint2(pack_bf16(c0, c1), pack_bf16(c2, c3));
            *(uint2*)(smem + SMF_W2L + off) =
                make_uint2(pack_bf16(v2.x - c0, v2.y - c1), pack_bf16(v2.z - c2, v2.w - c3));
        }
    }

    // ---- warp tiling: 2 warps along M (32 rows), 8 along N (16 cols each) ----
    const int m0 = (wid & 1) * 32;
    const int n0 = (wid >> 1) * 16;
    const int g = lane >> 3, rr = lane & 7;
    uint32_t aH0[2], aL0[2], b1H, b1L, b2H, b2L;
#pragma unroll
    for (int mb = 0; mb < 2; mb++) {
        const uint32_t o = (uint32_t)((m0 + mb * 16 + (g & 1) * 8 + rr) * SAB + (g >> 1) * 8) * 2;
        aH0[mb] = sb + SMF_AH + o;
        aL0[mb] = sb + SMF_AL + o;
    }
    {
        const uint32_t o = (uint32_t)((n0 + (g >> 1) * 8 + rr) * SAB + (g & 1) * 8) * 2;
        b1H = sb + SMF_W1H + o;
        b1L = sb + SMF_W1L + o;
        b2H = sb + SMF_W2H + o;
        b2L = sb + SMF_W2L + o;
    }
    const float* bs1 = (const float*)(smem + SMF_B1);
    const float* bs2 = (const float*)(smem + SMF_B2);

    // ---- persistent tile loop ----
    for (; tile < numTiles; tile += GEMM_GRID) {
        const int row0 = tile << 6;

        CP_WAIT0();
        __syncthreads();

        // convert stage -> split A (64 rows x 8 eighth-cols of 16)
        {
            const int r = tid >> 3;       // 0..63
            const int q = tid & 7;        // 16-col eighth
            const bool in = (row0 + r < M);
            const float* srow = stg + r * STG_F + q * 16;
#pragma unroll
            for (int j = 0; j < 4; j++) {
                const int col = q * 16 + j * 4;
                const uint32_t off = (uint32_t)(r * SAB + col) * 2;
                float4 va = in ? *(const float4*)(srow + j * 4) : make_float4(0.f, 0.f, 0.f, 0.f);
                float h0 = __bfloat162float(__float2bfloat16_rn(va.x));
                float h1 = __bfloat162float(__float2bfloat16_rn(va.y));
                float h2 = __bfloat162float(__float2bfloat16_rn(va.z));
                float h3 = __bfloat162float(__float2bfloat16_rn(va.w));
                *(uint2*)(smem + SMF_AH + off) = make_uint2(pack_bf16(h0, h1), pack_bf16(h2, h3));
                *(uint2*)(smem + SMF_AL + off) =
                    make_uint2(pack_bf16(va.x - h0, va.y - h1), pack_bf16(va.z - h2, va.w - h3));
            }
        }
        __syncthreads();

        // prefetch next tile (overlaps both GEMMs)
        const int nt = tile + GEMM_GRID;
        if (nt < numTiles) {
            const int nrow0 = nt << 6;
#pragma unroll
            for (int j = 0; j < 4; j++) {
                const int i = tid + j * 512;
                const int r = i >> 5, c16 = i & 31;
                if (nrow0 + r < M)
                    cp16(sb + SMF_STG + (uint32_t)(r * STG_F + c16 * 4) * 4,
                         A + (size_t)(nrow0 + r) * FEAT + c16 * 4);
            }
        }
        CP_COMMIT();

        // ================= GEMM1: acc = A @ W1^T =================
        float acc[2][2][4];
#pragma unroll
        for (int mb = 0; mb < 2; mb++)
#pragma unroll
            for (int o = 0; o < 2; o++)
#pragma unroll
                for (int q = 0; q < 4; q++) acc[mb][o][q] = 0.f;
        {
            uint32_t aH_[2] = {aH0[0], aH0[1]}, aL_[2] = {aL0[0], aL0[1]};
            uint32_t bH_ = b1H, bL_ = b1L;
#pragma unroll
            for (int kk = 0; kk < 8; kk++) {
                uint32_t ah[2][4], al[2][4], bb[4];
                ldsm_x4(ah[0], aH_[0]); ldsm_x4(ah[1], aH_[1]);
                ldsm_x4(al[0], aL_[0]); ldsm_x4(al[1], aL_[1]);
                ldsm_x4(bb, bH_);
#pragma unroll
                for (int mb = 0; mb < 2; mb++)
#pragma unroll
                    for (int o = 0; o < 2; o++) {
                        const uint32_t* b = &bb[o * 2];
                        mma_bf16(acc[mb][o], ah[mb], b);
                        mma_bf16(acc[mb][o], al[mb], b);
                    }
                ldsm_x4(bb, bL_);
#pragma unroll
                for (int mb = 0; mb < 2; mb++)
#pragma unroll
                    for (int o = 0; o < 2; o++)
                        mma_bf16(acc[mb][o], ah[mb], &bb[o * 2]);
#pragma unroll
                for (int i = 0; i < 2; i++) { aH_[i] += 32; aL_[i] += 32; }
                bH_ += 32; bL_ += 32;
            }
        }
        __syncthreads();

        // ---- h1 = relu(acc + b1) split-packed into A buffers ----
#pragma unroll
        for (int mb = 0; mb < 2; mb++) {
            const int r0 = m0 + mb * 16 + (lane >> 2);
#pragma unroll
            for (int o = 0; o < 2; o++) {
                const int col = n0 + o * 8 + (lane & 3) * 2;
                const float c0 = bs1[col], c1 = bs1[col + 1];
                const uint32_t off0 = (uint32_t)(r0 * SAB + col) * 2;
                const uint32_t off8 = (uint32_t)((r0 + 8) * SAB + col) * 2;
                float v0 = fmaxf(acc[mb][o][0] + c0, 0.f);
                float v1 = fmaxf(acc[mb][o][1] + c1, 0.f);
                float h0 = __bfloat162float(__float2bfloat16_rn(v0));
                float h1 = __bfloat162float(__float2bfloat16_rn(v1));
                *(uint32_t*)(smem + SMF_AH + off0) = pack_bf16(h0, h1);
                *(uint32_t*)(smem + SMF_AL + off0) = pack_bf16(v0 - h0, v1 - h1);
                float v2 = fmaxf(acc[mb][o][2] + c0, 0.f);
                float v3 = fmaxf(acc[mb][o][3] + c1, 0.f);
                float h2 = __bfloat162float(__float2bfloat16_rn(v2));
                float h3 = __bfloat162float(__float2bfloat16_rn(v3));
                *(uint32_t*)(smem + SMF_AH + off8) = pack_bf16(h2, h3);
                *(uint32_t*)(smem + SMF_AL + off8) = pack_bf16(v2 - h2, v3 - h3);
            }
        }
        __syncthreads();

        // ================= GEMM2: acc = h1 @ W2^T =================
#pragma unroll
        for (int mb = 0; mb < 2; mb++)
#pragma unroll
            for (int o = 0; o < 2; o++)
#pragma unroll
                for (int q = 0; q < 4; q++) acc[mb][o][q] = 0.f;
        {
            uint32_t aH_[2] = {aH0[0], aH0[1]}, aL_[2] = {aL0[0], aL0[1]};
            uint32_t bH_ = b2H, bL_ = b2L;
#pragma unroll
            for (int kk = 0; kk < 8; kk++) {
                uint32_t ah[2][4], al[2][4], bb[4];
                ldsm_x4(ah[0], aH_[0]); ldsm_x4(ah[1], aH_[1]);
                ldsm_x4(al[0], aL_[0]); ldsm_x4(al[1], aL_[1]);
                ldsm_x4(bb, bH_);
#pragma unroll
                for (int mb = 0; mb < 2; mb++)
#pragma unroll
                    for (int o = 0; o < 2; o++) {
                        const uint32_t* b = &bb[o * 2];
                        mma_bf16(acc[mb][o], ah[mb], b);
                        mma_bf16(acc[mb][o], al[mb], b);
                    }
                ldsm_x4(bb, bL_);
#pragma unroll
                for (int mb = 0; mb < 2; mb++)
#pragma unroll
                    for (int o = 0; o < 2; o++)
                        mma_bf16(acc[mb][o], ah[mb], &bb[o * 2]);
#pragma unroll
                for (int i = 0; i < 2; i++) { aH_[i] += 32; aL_[i] += 32; }
                bH_ += 32; bL_ += 32;
            }
        }
        __syncthreads();

        // ---- epilogue: relu(acc + b2) -> C ----
#pragma unroll
        for (int mb = 0; mb < 2; mb++) {
            const int rbase = row0 + m0 + mb * 16 + (lane >> 2);
#pragma unroll
            for (int o = 0; o < 2; o++) {
                const int col = n0 + o * 8 + (lane & 3) * 2;
                const float c0 = bs2[col], c1 = bs2[col + 1];
                if (rbase < M) {
                    float2 v = make_float2(fmaxf(acc[mb][o][0] + c0, 0.f),
                                           fmaxf(acc[mb][o][1] + c1, 0.f));
                    *(float2*)(C + (size_t)rbase * FEAT + col) = v;
                }
                if (rbase + 8 < M) {
                    float2 v = make_float2(fmaxf(acc[mb][o][2] + c0, 0.f),
                                           fmaxf(acc[mb][o][3] + c1, 0.f));
                    *(float2*)(C + (size_t)(rbase + 8) * FEAT + col) = v;
                }
            }
        }
    }
}

// ===========================================================================
// Two-phase global mean pool (R15)
// ===========================================================================
__device__ __forceinline__ void graph_range(const void* batch, int is64, int gph,
                                            int& start, int& end) {
    const long long* b64 = (const long long*)batch;
    const int* b32 = (const int*)batch;
    int lo = 0, hi = N_NODES;
    while (lo < hi) {
        int mid = (lo + hi) >> 1;
        long long v = is64 ? b64[mid] : (long long)b32[mid];
        if (v < (long long)gph) lo = mid + 1; else hi = mid;
    }
    start = lo;
    hi = N_NODES;
    while (lo < hi) {
        int mid = (lo + hi) >> 1;
        long long v = is64 ? b64[mid] : (long long)b32[mid];
        if (v < (long long)gph + 1) lo = mid + 1; else hi = mid;
    }
    end = lo;
}

__global__ void pool_partial_kernel(const float* __restrict__ h,
                                    const void* __restrict__ batch,
                                    float* __restrict__ poolacc) {
    const int gph = blockIdx.x;
    const int seg = blockIdx.y;
    const int c = threadIdx.x;
    int start, end;
    graph_range(batch, g_idx64, gph, start, end);
    const int len = end - start;
    const int s0 = start + (int)(((long long)len * seg) / POOL_SEGS);
    const int s1 = start + (int)(((long long)len * (seg + 1)) / POOL_SEGS);
    float s = 0.f;
    for (int r = s0; r < s1; r++) s += h[(size_t)r * FEAT + c];
    if (s1 > s0) atomicAdd(&poolacc[gph * FEAT + c], s);
}

__global__ void pool_final_kernel(const float* __restrict__ poolacc,
                                  const void* __restrict__ batch,
                                  float* __restrict__ out_pool) {
    const int gph = blockIdx.x;
    const int c = threadIdx.x;
    int start, end;
    graph_range(batch, g_idx64, gph, start, end);
    out_pool[gph * FEAT + c] = poolacc[gph * FEAT + c] / fmaxf((float)(end - start), 1.f);
}

// ===========================================================================
extern "C" void kernel_launch(void* const* d_in, const int* in_sizes, int n_in,
                              void* d_out, int out_size) {
    const float* x   = (const float*)d_in[0];
    const void*  ei  = d_in[1];
    const void*  bat = d_in[2];
    const float* W1 = (const float*)d_in[3];
    const float* b1 = (const float*)d_in[4];
    const float* W2 = (const float*)d_in[5];
    const float* b2 = (const float*)d_in[6];
    const float* W3 = (const float*)d_in[7];
    const float* b3 = (const float*)d_in[8];
    const float* W4 = (const float*)d_in[9];
    const float* b4 = (const float*)d_in[10];

    float* out      = (float*)d_out;
    float* out_pool = out;
    float* out_h    = out + N_GRAPHS * FEAT;

    float *bufA, *bufB, *poolacc;
    int *deg, *rowptr, *cursor, *csrsrc, *blocksum, *blockoff;
    cudaGetSymbolAddress((void**)&bufA, g_bufA);
    cudaGetSymbolAddress((void**)&bufB, g_bufB);
    cudaGetSymbolAddress((void**)&poolacc, g_poolacc);
    cudaGetSymbolAddress((void**)&deg, g_deg);
    cudaGetSymbolAddress((void**)&rowptr, g_rowptr);
    cudaGetSymbolAddress((void**)&cursor, g_cursor);
    cudaGetSymbolAddress((void**)&csrsrc, g_csrsrc);
    cudaGetSymbolAddress((void**)&blocksum, g_blocksum);
    cudaGetSymbolAddress((void**)&blockoff, g_blockoff);

    cudaFuncSetAttribute(mlp_fused_kernel,
                         cudaFuncAttributeMaxDynamicSharedMemorySize, SMF_TOTAL);

    const int edge_blocks = (N_EDGES + 255) / 256;
    const int agg_blocks = (N_NODES + 7) / 8;

    // ---- CSR build ----
    detect_kernel<<<1, 32>>>((const int*)ei);
    cudaMemsetAsync(deg, 0, N_NODES * sizeof(int));
    cudaMemsetAsync(poolacc, 0, N_GRAPHS * FEAT * sizeof(float));
    hist_kernel<<<edge_blocks, 256>>>(ei, deg);
    scanA_kernel<<<SCAN_BLOCKS, 256>>>(deg, blocksum);
    scanB_kernel<<<1, 128>>>(blocksum, blockoff, rowptr);
    scanC_kernel<<<SCAN_BLOCKS, 256>>>(deg, blockoff, rowptr, cursor);
    fill_kernel<<<edge_blocks, 256>>>(ei, cursor, csrsrc);

    // ---- Layer 1 ----
    agg_kernel<<<agg_blocks, 256>>>(x, bufA, rowptr, csrsrc);
    mlp_fused_kernel<<<GEMM_GRID, 512, SMF_TOTAL>>>(bufA, W1, b1, W2, b2, bufB, N_NODES);

    // ---- Layer 2 ----
    agg_kernel<<<agg_blocks, 256>>>(bufB, bufA, rowptr, csrsrc);
    mlp_fused_kernel<<<GEMM_GRID, 512, SMF_TOTAL>>>(bufA, W3, b3, W4, b4, out_h, N_NODES);

    // ---- Two-phase global mean pool ----
    dim3 pgrid(N_GRAPHS, POOL_SEGS);
    pool_partial_kernel<<<pgrid, FEAT>>>(out_h, bat, poolacc);
    pool_final_kernel<<<N_GRAPHS, FEAT>>>(poolacc, bat, out_pool);
}